// round 14
// baseline (speedup 1.0000x reference)
#include <cuda_runtime.h>
#include <cuda_bf16.h>
#include <cstdint>
#include <cstddef>

#define N_TOK   131072
#define DIM     64
#define KCODES  1024
#define KHALF   512
#define QBLOCKS 512
#define MARGIN  6e-3f            // >=10x bf16 screen error bound

// Output layout (float32, flattened tuple order)
#define OUT_Q    ((size_t)1)
#define OUT_PERP ((size_t)1 + (size_t)N_TOK * DIM)
#define OUT_IDX  ((size_t)2 + (size_t)N_TOK * DIM)

typedef unsigned long long u64;

// smem map (bytes): e2 @0 (2KB) | A @2048 (128 rows x 144B) | B @20480 (512 rows x 144B)
#define RS      144              // padded row stride (bank-conflict-free ldmatrix)
#define SM_A    2048
#define SM_B    20480
#define SMEM_SZ (20480 + 512 * RS)   // 94208

// ---------------- device scratch (no allocations allowed) ----------------
__device__ float    g_e2[KCODES];
__device__ u64      g_key[N_TOK];     // (dist_bits<<32)|idx, merged by atomicMin
__device__ int      g_counts[KCODES];
__device__ double   g_block_sse[QBLOCKS];
__device__ uint32_t g_xbf[N_TOK * DIM / 2];    // bf16x2-packed inputs
__device__ uint32_t g_cbbf[KCODES * DIM / 2];  // bf16x2-packed codebook

// ---------------- packed f32x2 helpers (frozen exact-rescore path) -------
__device__ __forceinline__ void ffma2(u64& d, u64 a, u64 b) {
    asm("fma.rn.f32x2 %0, %1, %2, %0;" : "+l"(d) : "l"(a), "l"(b));
}
__device__ __forceinline__ float2 unpack2(u64 v) {
    float2 f; asm("mov.b64 {%0, %1}, %2;" : "=f"(f.x), "=f"(f.y) : "l"(v)); return f;
}
__device__ __forceinline__ uint32_t bfpack(float lo, float hi) {
    uint32_t r; asm("cvt.rn.bf16x2.f32 %0, %1, %2;" : "=r"(r) : "f"(hi), "f"(lo));
    return r;
}

// ---------------- warp-MMA helpers (plain-target PTX, sm_80+) ------------
__device__ __forceinline__ void ldsm4(uint32_t* r, uint32_t addr) {
    asm volatile("ldmatrix.sync.aligned.m8n8.x4.shared.b16 {%0,%1,%2,%3}, [%4];"
        : "=r"(r[0]), "=r"(r[1]), "=r"(r[2]), "=r"(r[3]) : "r"(addr));
}
__device__ __forceinline__ void mma16816(float* d, const uint32_t* a,
                                         const uint32_t* b, const float* c) {
    asm volatile("mma.sync.aligned.m16n8k16.row.col.f32.bf16.bf16.f32 "
        "{%0,%1,%2,%3}, {%4,%5,%6,%7}, {%8,%9}, {%10,%11,%12,%13};"
        : "=f"(d[0]), "=f"(d[1]), "=f"(d[2]), "=f"(d[3])
        : "r"(a[0]), "r"(a[1]), "r"(a[2]), "r"(a[3]), "r"(b[0]), "r"(b[1]),
          "f"(c[0]), "f"(c[1]), "f"(c[2]), "f"(c[3]));
}

// ---------------- kernel 0: prep (e2 frozen, keys, counts, bf16 convert) --
__global__ void vq_prep_kernel(const float* __restrict__ x, const float* __restrict__ cb) {
    const int i = blockIdx.x * 256 + threadIdx.x;      // [0, N_TOK)
    g_key[i] = 0xFFFFFFFFFFFFFFFFull;

    const float2* xp = reinterpret_cast<const float2*>(x);
    #pragma unroll 4
    for (int j = 0; j < 32; ++j) {
        int p = j * N_TOK + i;
        float2 v = xp[p];
        g_xbf[p] = bfpack(v.x, v.y);
    }

    if (i < KCODES) {
        const float* row = cb + (size_t)i * DIM;
        float s0 = 0.f, s1 = 0.f, s2 = 0.f, s3 = 0.f;   // FROZEN e2 order
        #pragma unroll
        for (int j = 0; j < DIM; j += 4) {
            s0 = fmaf(row[j+0], row[j+0], s0);
            s1 = fmaf(row[j+1], row[j+1], s1);
            s2 = fmaf(row[j+2], row[j+2], s2);
            s3 = fmaf(row[j+3], row[j+3], s3);
        }
        g_e2[i] = (s0 + s1) + (s2 + s3);
        g_counts[i] = 0;
        const float2* cr = reinterpret_cast<const float2*>(row);
        #pragma unroll
        for (int w = 0; w < 32; ++w) {
            float2 v = cr[w];
            g_cbbf[i * 32 + w] = bfpack(v.x, v.y);
        }
    }
}

// ---------------- kernel 1: bf16 HMMA screen + exact rescore --------------
// Grid 2048 = 1024 token-tiles x 2 code-halves; 128 thr (4 warps).
// Warp w screens rows [w*32, w*32+32) x 512 codes via mma.sync m16n8k16.
// Screen key ds = fmaf(dot_bf16, -2, e2) (x^2 cancels per-token).
// Candidates (ds < running_min + MARGIN) recorded per thread-subset, then
// exactly rescored with the FROZEN fp32 chain and merged via the proven
// lexicographic (dist_bits, idx) atomicMin.
__global__ void __launch_bounds__(128)
vq_argmin_kernel(const float* __restrict__ x, const float* __restrict__ cb) {
    extern __shared__ __align__(128) char smem[];
    const int tid  = threadIdx.x;
    const int wid  = tid >> 5;
    const int lid  = tid & 31;
    const int half = blockIdx.x & 1;
    const int tile = blockIdx.x >> 1;
    const uint32_t sb = (uint32_t)__cvta_generic_to_shared(smem);

    float* s_e2 = reinterpret_cast<float*>(smem);

    // stage e2 half
    #pragma unroll
    for (int j = 0; j < 4; ++j)
        s_e2[j * 128 + tid] = g_e2[half * KHALF + j * 128 + tid];

    // stage A: 128 token rows x 32 bf16x2 words into RS-padded rows
    {
        const uint32_t* src = g_xbf + (size_t)tile * 128 * 32;
        #pragma unroll
        for (int j = 0; j < 32; ++j) {
            int flat = j * 128 + tid;
            int row = flat >> 5, w = flat & 31;
            *reinterpret_cast<uint32_t*>(smem + SM_A + row * RS + w * 4) = src[flat];
        }
    }
    // stage B: 512 code rows x 32 words
    {
        const uint32_t* src = g_cbbf + (size_t)half * KHALF * 32;
        #pragma unroll
        for (int j = 0; j < 128; ++j) {
            int flat = j * 128 + tid;
            int row = flat >> 5, w = flat & 31;
            *reinterpret_cast<uint32_t*>(smem + SM_B + row * RS + w * 4) = src[flat];
        }
    }
    __syncthreads();

    // Preload A fragments: 2 m-blocks x 4 k-steps x 4 regs
    uint32_t afr[2][4][4];
    {
        const int rl = lid & 15;
        const int kh = ((lid >> 4) & 1) * 8;
        #pragma unroll
        for (int mb = 0; mb < 2; ++mb) {
            int mbase = wid * 32 + mb * 16;
            #pragma unroll
            for (int s = 0; s < 4; ++s)
                ldsm4(afr[mb][s], sb + SM_A + (mbase + rl) * RS + (s * 16 + kh) * 2);
        }
    }

    const int q = lid & 3;
    float    smin[4] = {3.4e38f, 3.4e38f, 3.4e38f, 3.4e38f};
    uint32_t mask[4][4] = {};

    const uint32_t brow_base = sb + SM_B + (lid & 7) * RS;
    const uint32_t bk = ((lid >> 3) * 8) * 2;

    #pragma unroll 2
    for (int nb = 0; nb < 64; ++nb) {
        uint32_t bfr[8];
        uint32_t br = brow_base + nb * 8 * RS;
        ldsm4(bfr + 0, br + bk);          // k 0..31  -> ksteps 0,1
        ldsm4(bfr + 4, br + 64 + bk);     // k 32..63 -> ksteps 2,3
        float c0[4] = {0.f, 0.f, 0.f, 0.f};
        float c1[4] = {0.f, 0.f, 0.f, 0.f};
        #pragma unroll
        for (int s = 0; s < 4; ++s) {
            mma16816(c0, afr[0][s], bfr + 2 * s, c0);
            mma16816(c1, afr[1][s], bfr + 2 * s, c1);
        }
        int colb = nb * 8 + 2 * q;
        float ea = s_e2[colb], eb = s_e2[colb + 1];
        const int mw = nb >> 4;
        const int bshift = (nb & 15) << 1;
        float ds;
        #define SCR(j, val, e2v, hb) \
            ds = fmaf(val, -2.0f, e2v); \
            if (ds < smin[j] + MARGIN) mask[j][mw] |= 1u << (bshift | hb); \
            if (ds < smin[j]) smin[j] = ds;
        SCR(0, c0[0], ea, 0) SCR(0, c0[1], eb, 1)
        SCR(1, c0[2], ea, 0) SCR(1, c0[3], eb, 1)
        SCR(2, c1[0], ea, 0) SCR(2, c1[1], eb, 1)
        SCR(3, c1[2], ea, 0) SCR(3, c1[3], eb, 1)
        #undef SCR
    }

    // ----- exact rescore of candidates (FROZEN arithmetic) -----
    const int rbase = tile * 128 + wid * 32 + (lid >> 2);
    #pragma unroll 1
    for (int j = 0; j < 4; ++j) {
        const int token = rbase + j * 8;

        u64 px[DIM / 2];
        const ulonglong2* rx = reinterpret_cast<const ulonglong2*>(x + (size_t)token * DIM);
        #pragma unroll
        for (int i = 0; i < DIM / 4; ++i) {
            ulonglong2 v = rx[i]; px[2*i] = v.x; px[2*i+1] = v.y;
        }
        u64 qa = 0ull;
        #pragma unroll
        for (int p = 0; p < DIM / 2; ++p) ffma2(qa, px[p], px[p]);
        float2 fq = unpack2(qa);
        float x2 = fq.x + fq.y;

        float bestd = 3.4e38f;
        int   bi    = 0;
        #pragma unroll 1
        for (int w_ = 0; w_ < 4; ++w_) {
            uint32_t m = mask[j][w_];
            while (m) {
                int b = __ffs(m) - 1; m &= m - 1;
                int idx = (w_ << 5) | b;                   // ascending -> c ascending
                int c = (idx >> 1) * 8 + 2 * q + (idx & 1);
                int code = half * KHALF + c;
                const ulonglong2* e = reinterpret_cast<const ulonglong2*>(cb + (size_t)code * DIM);
                u64 a = 0ull;                              // frozen single chain
                #pragma unroll
                for (int p = 0; p < DIM / 4; ++p) {
                    ulonglong2 v = e[p];
                    ffma2(a, px[2*p],   v.x);
                    ffma2(a, px[2*p+1], v.y);
                }
                float2 f = unpack2(a);
                float d = fmaf(f.x + f.y, -2.0f, x2) + s_e2[c];
                if (d < bestd) { bestd = d; bi = code; }
            }
        }
        u64 key = ((u64)__float_as_uint(bestd) << 32) | (unsigned)bi;
        atomicMin(&g_key[token], key);
    }
}

// ---------------- kernel 2: quantize + MSE partials + histogram ----------
__global__ void __launch_bounds__(256)
vq_quantize_kernel(const float* __restrict__ x, const float* __restrict__ cb,
                   float* __restrict__ dout) {
    __shared__ int   sbins[KCODES];
    __shared__ float swarp[8];

    for (int i = threadIdx.x; i < KCODES; i += 256) sbins[i] = 0;
    __syncthreads();

    const int dim  = threadIdx.x & 63;
    const int sub  = threadIdx.x >> 6;
    const int base = blockIdx.x * 256;
    float* out_idx_f = dout + OUT_IDX;

    float lsum = 0.f;
    #pragma unroll 4
    for (int it = 0; it < 64; ++it) {
        int t   = base + it * 4 + sub;
        int idx = (int)(unsigned)g_key[t];
        float qv = cb[(size_t)idx * DIM + dim];
        float xv = x[(size_t)t * DIM + dim];
        float df = qv - xv;
        dout[OUT_Q + (size_t)t * DIM + dim] = xv + df;
        lsum = fmaf(df, df, lsum);
        if (dim == 0) {
            atomicAdd(&sbins[idx], 1);
            out_idx_f[t] = (float)idx;
        }
    }

    #pragma unroll
    for (int o = 16; o > 0; o >>= 1) lsum += __shfl_down_sync(0xffffffffu, lsum, o);
    if ((threadIdx.x & 31) == 0) swarp[threadIdx.x >> 5] = lsum;
    __syncthreads();
    if (threadIdx.x == 0) {
        float s = 0.f;
        #pragma unroll
        for (int w = 0; w < 8; ++w) s += swarp[w];
        g_block_sse[blockIdx.x] = (double)s;
    }
    for (int i = threadIdx.x; i < KCODES; i += 256) {
        int c = sbins[i];
        if (c) atomicAdd(&g_counts[i], c);
    }
}

// ---------------- kernel 3: finalize loss + perplexity -------------------
__global__ void vq_finalize_kernel(float* __restrict__ dout) {
    __shared__ double sd[256];
    const int tid = threadIdx.x;

    double s = 0.0;
    for (int i = tid; i < QBLOCKS; i += 256) s += g_block_sse[i];
    sd[tid] = s;
    __syncthreads();
    #pragma unroll
    for (int o = 128; o > 0; o >>= 1) {
        if (tid < o) sd[tid] += sd[tid + o];
        __syncthreads();
    }
    double sse = sd[0];
    __syncthreads();

    double h = 0.0;
    for (int i = tid; i < KCODES; i += 256) {
        float p = (float)g_counts[i] * (1.0f / (float)N_TOK);
        h += (double)(p * logf(p + 1e-10f));
    }
    sd[tid] = h;
    __syncthreads();
    #pragma unroll
    for (int o = 128; o > 0; o >>= 1) {
        if (tid < o) sd[tid] += sd[tid + o];
        __syncthreads();
    }

    if (tid == 0) {
        float mse = (float)(sse / ((double)N_TOK * (double)DIM));
        dout[0]        = mse + 0.25f * mse;
        dout[OUT_PERP] = expf((float)(-sd[0]));
    }
}

// ---------------- launch ---------------------------------------------------
extern "C" void kernel_launch(void* const* d_in, const int* in_sizes, int n_in,
                              void* d_out, int out_size) {
    const float* x  = (const float*)d_in[0];
    const float* cb = (const float*)d_in[1];
    if (n_in >= 2 && in_sizes[0] == KCODES * DIM && in_sizes[1] == N_TOK * DIM) {
        const float* t = x; x = cb; cb = t;
    }
    float* out = (float*)d_out;

    cudaFuncSetAttribute(vq_argmin_kernel,
                         cudaFuncAttributeMaxDynamicSharedMemorySize, SMEM_SZ);

    vq_prep_kernel<<<N_TOK / 256, 256>>>(x, cb);
    vq_argmin_kernel<<<(N_TOK / 128) * 2, 128, SMEM_SZ>>>(x, cb);
    vq_quantize_kernel<<<QBLOCKS, 256>>>(x, cb, out);
    vq_finalize_kernel<<<1, 256>>>(out);
}

// round 15
// speedup vs baseline: 2.3472x; 2.3472x over previous
#include <cuda_runtime.h>
#include <cuda_bf16.h>
#include <cstdint>
#include <cstddef>

#define N_TOK   131072
#define DIM     64
#define KCODES  1024
#define KHALF   512
#define QBLOCKS 512
#define MGN     8e-4f            // dot-margin: >=5x bf16 screen error bound

// Output layout (float32, flattened tuple order)
#define OUT_Q    ((size_t)1)
#define OUT_PERP ((size_t)1 + (size_t)N_TOK * DIM)
#define OUT_IDX  ((size_t)2 + (size_t)N_TOK * DIM)

typedef unsigned long long u64;

// smem map (bytes): e2 @0 (2KB) | A @2048 (128 rows x 144B) | B @20480 (512 rows x 144B)
#define RS      144
#define SM_A    2048
#define SM_B    20480
#define SMEM_SZ (20480 + 512 * RS)   // 94208

// ---------------- device scratch (no allocations allowed) ----------------
__device__ float    g_e2[KCODES];
__device__ u64      g_key[N_TOK];     // (dist_bits<<32)|idx, merged by atomicMin
__device__ int      g_counts[KCODES];
__device__ double   g_block_sse[QBLOCKS];
__device__ uint32_t g_xbf[N_TOK * DIM / 2];    // bf16x2-packed inputs
__device__ uint32_t g_cbbf[KCODES * DIM / 2];  // bf16x2-packed codebook

// ---------------- packed f32x2 helpers (frozen exact-rescore path) -------
__device__ __forceinline__ void ffma2(u64& d, u64 a, u64 b) {
    asm("fma.rn.f32x2 %0, %1, %2, %0;" : "+l"(d) : "l"(a), "l"(b));
}
__device__ __forceinline__ float2 unpack2(u64 v) {
    float2 f; asm("mov.b64 {%0, %1}, %2;" : "=f"(f.x), "=f"(f.y) : "l"(v)); return f;
}
__device__ __forceinline__ uint32_t bfpack(float lo, float hi) {
    uint32_t r; asm("cvt.rn.bf16x2.f32 %0, %1, %2;" : "=r"(r) : "f"(hi), "f"(lo));
    return r;
}

// ---------------- warp-MMA helpers (plain-target PTX, sm_80+) ------------
__device__ __forceinline__ void ldsm4(uint32_t* r, uint32_t addr) {
    asm volatile("ldmatrix.sync.aligned.m8n8.x4.shared.b16 {%0,%1,%2,%3}, [%4];"
        : "=r"(r[0]), "=r"(r[1]), "=r"(r[2]), "=r"(r[3]) : "r"(addr));
}
__device__ __forceinline__ void mma16816(float* d, const uint32_t* a,
                                         const uint32_t* b, const float* c) {
    asm volatile("mma.sync.aligned.m16n8k16.row.col.f32.bf16.bf16.f32 "
        "{%0,%1,%2,%3}, {%4,%5,%6,%7}, {%8,%9}, {%10,%11,%12,%13};"
        : "=f"(d[0]), "=f"(d[1]), "=f"(d[2]), "=f"(d[3])
        : "r"(a[0]), "r"(a[1]), "r"(a[2]), "r"(a[3]), "r"(b[0]), "r"(b[1]),
          "f"(c[0]), "f"(c[1]), "f"(c[2]), "f"(c[3]));
}

// ---------------- kernel 0: prep (e2 frozen, keys, counts, bf16 convert) --
__global__ void vq_prep_kernel(const float* __restrict__ x, const float* __restrict__ cb) {
    const int i = blockIdx.x * 256 + threadIdx.x;      // [0, N_TOK)
    g_key[i] = 0xFFFFFFFFFFFFFFFFull;

    const float2* xp = reinterpret_cast<const float2*>(x);
    #pragma unroll 4
    for (int j = 0; j < 32; ++j) {
        int p = j * N_TOK + i;
        float2 v = xp[p];
        g_xbf[p] = bfpack(v.x, v.y);
    }

    if (i < KCODES) {
        const float* row = cb + (size_t)i * DIM;
        float s0 = 0.f, s1 = 0.f, s2 = 0.f, s3 = 0.f;   // FROZEN e2 order
        #pragma unroll
        for (int j = 0; j < DIM; j += 4) {
            s0 = fmaf(row[j+0], row[j+0], s0);
            s1 = fmaf(row[j+1], row[j+1], s1);
            s2 = fmaf(row[j+2], row[j+2], s2);
            s3 = fmaf(row[j+3], row[j+3], s3);
        }
        g_e2[i] = (s0 + s1) + (s2 + s3);
        g_counts[i] = 0;
        const float2* cr = reinterpret_cast<const float2*>(row);
        #pragma unroll
        for (int w = 0; w < 32; ++w) {
            float2 v = cr[w];
            g_cbbf[i * 32 + w] = bfpack(v.x, v.y);
        }
    }
}

// ---------------- kernel 1: two-pass bf16 HMMA screen + exact rescore -----
// Pass 1: max(dot) over the half (no mask). Pass 2: identical MMAs, mask
// codes with dot > smax_final - MGN (tight; ~3 candidates/half expected).
// Rescore: FROZEN fp32 chain + lexicographic (dist_bits, idx) atomicMin
// (both proven exact across all passing rounds).
__global__ void __launch_bounds__(128)
vq_argmin_kernel(const float* __restrict__ x, const float* __restrict__ cb) {
    extern __shared__ __align__(128) char smem[];
    const int tid  = threadIdx.x;
    const int wid  = tid >> 5;
    const int lid  = tid & 31;
    const int half = blockIdx.x & 1;
    const int tile = blockIdx.x >> 1;
    const uint32_t sb = (uint32_t)__cvta_generic_to_shared(smem);

    float* s_e2 = reinterpret_cast<float*>(smem);
    #pragma unroll
    for (int j = 0; j < 4; ++j)
        s_e2[j * 128 + tid] = g_e2[half * KHALF + j * 128 + tid];

    // stage A: 128 token rows x 32 bf16x2 words into RS-padded rows
    {
        const uint32_t* src = g_xbf + (size_t)tile * 128 * 32;
        #pragma unroll
        for (int j = 0; j < 32; ++j) {
            int flat = j * 128 + tid;
            int row = flat >> 5, w = flat & 31;
            *reinterpret_cast<uint32_t*>(smem + SM_A + row * RS + w * 4) = src[flat];
        }
    }
    // stage B: 512 code rows x 32 words
    {
        const uint32_t* src = g_cbbf + (size_t)half * KHALF * 32;
        #pragma unroll
        for (int j = 0; j < 128; ++j) {
            int flat = j * 128 + tid;
            int row = flat >> 5, w = flat & 31;
            *reinterpret_cast<uint32_t*>(smem + SM_B + row * RS + w * 4) = src[flat];
        }
    }
    __syncthreads();

    // Preload A fragments: 2 m-blocks x 4 k-steps x 4 regs
    uint32_t afr[2][4][4];
    {
        const int rl = lid & 15;
        const int kh = ((lid >> 4) & 1) * 8;
        #pragma unroll
        for (int mb = 0; mb < 2; ++mb) {
            int mbase = wid * 32 + mb * 16;
            #pragma unroll
            for (int s = 0; s < 4; ++s)
                ldsm4(afr[mb][s], sb + SM_A + (mbase + rl) * RS + (s * 16 + kh) * 2);
        }
    }

    const int q = lid & 3;
    const uint32_t brow_base = sb + SM_B + (lid & 7) * RS;
    const uint32_t bk = ((lid >> 3) * 8) * 2;

    // ---- pass 1: final max(dot) per token row ----
    float smax[4] = {-3.4e38f, -3.4e38f, -3.4e38f, -3.4e38f};
    #pragma unroll 2
    for (int nb = 0; nb < 64; ++nb) {
        uint32_t bfr[8];
        uint32_t br = brow_base + nb * 8 * RS;
        ldsm4(bfr + 0, br + bk);
        ldsm4(bfr + 4, br + 64 + bk);
        float c0[4] = {0.f, 0.f, 0.f, 0.f};
        float c1[4] = {0.f, 0.f, 0.f, 0.f};
        #pragma unroll
        for (int s = 0; s < 4; ++s) {
            mma16816(c0, afr[0][s], bfr + 2 * s, c0);
            mma16816(c1, afr[1][s], bfr + 2 * s, c1);
        }
        smax[0] = fmaxf(smax[0], fmaxf(c0[0], c0[1]));
        smax[1] = fmaxf(smax[1], fmaxf(c0[2], c0[3]));
        smax[2] = fmaxf(smax[2], fmaxf(c1[0], c1[1]));
        smax[3] = fmaxf(smax[3], fmaxf(c1[2], c1[3]));
    }

    // ---- pass 2: mask codes with dot > smax - MGN (final-min screen) ----
    uint32_t mask[4][4] = {};
    #pragma unroll 2
    for (int nb = 0; nb < 64; ++nb) {
        uint32_t bfr[8];
        uint32_t br = brow_base + nb * 8 * RS;
        ldsm4(bfr + 0, br + bk);
        ldsm4(bfr + 4, br + 64 + bk);
        float c0[4] = {0.f, 0.f, 0.f, 0.f};
        float c1[4] = {0.f, 0.f, 0.f, 0.f};
        #pragma unroll
        for (int s = 0; s < 4; ++s) {
            mma16816(c0, afr[0][s], bfr + 2 * s, c0);
            mma16816(c1, afr[1][s], bfr + 2 * s, c1);
        }
        const int mw = nb >> 4;
        const int bshift = (nb & 15) << 1;
        #define SCR(j, val, hb) \
            if ((val) > smax[j] - MGN) mask[j][mw] |= 1u << (bshift | hb);
        SCR(0, c0[0], 0) SCR(0, c0[1], 1)
        SCR(1, c0[2], 0) SCR(1, c0[3], 1)
        SCR(2, c1[0], 0) SCR(2, c1[1], 1)
        SCR(3, c1[2], 0) SCR(3, c1[3], 1)
        #undef SCR
    }

    // ----- exact rescore of candidates (FROZEN arithmetic) -----
    const int rbase = tile * 128 + wid * 32 + (lid >> 2);
    #pragma unroll 1
    for (int j = 0; j < 4; ++j) {
        const int token = rbase + j * 8;

        u64 px[DIM / 2];
        const ulonglong2* rx = reinterpret_cast<const ulonglong2*>(x + (size_t)token * DIM);
        #pragma unroll
        for (int i = 0; i < DIM / 4; ++i) {
            ulonglong2 v = rx[i]; px[2*i] = v.x; px[2*i+1] = v.y;
        }
        u64 qa = 0ull;
        #pragma unroll
        for (int p = 0; p < DIM / 2; ++p) ffma2(qa, px[p], px[p]);
        float2 fq = unpack2(qa);
        float x2 = fq.x + fq.y;

        float bestd = 3.4e38f;
        int   bi    = 0;
        #pragma unroll 1
        for (int w_ = 0; w_ < 4; ++w_) {
            uint32_t m = mask[j][w_];
            while (m) {
                int b = __ffs(m) - 1; m &= m - 1;
                int idx = (w_ << 5) | b;                   // ascending -> c ascending
                int c = (idx >> 1) * 8 + 2 * q + (idx & 1);
                int code = half * KHALF + c;
                const ulonglong2* e = reinterpret_cast<const ulonglong2*>(cb + (size_t)code * DIM);
                u64 a = 0ull;                              // frozen single chain
                #pragma unroll
                for (int p = 0; p < DIM / 4; ++p) {
                    ulonglong2 v = e[p];
                    ffma2(a, px[2*p],   v.x);
                    ffma2(a, px[2*p+1], v.y);
                }
                float2 f = unpack2(a);
                float d = fmaf(f.x + f.y, -2.0f, x2) + s_e2[c];
                if (d < bestd) { bestd = d; bi = code; }
            }
        }
        u64 key = ((u64)__float_as_uint(bestd) << 32) | (unsigned)bi;
        atomicMin(&g_key[token], key);
    }
}

// ---------------- kernel 2: quantize + MSE partials + histogram ----------
__global__ void __launch_bounds__(256)
vq_quantize_kernel(const float* __restrict__ x, const float* __restrict__ cb,
                   float* __restrict__ dout) {
    __shared__ int   sbins[KCODES];
    __shared__ float swarp[8];

    for (int i = threadIdx.x; i < KCODES; i += 256) sbins[i] = 0;
    __syncthreads();

    const int dim  = threadIdx.x & 63;
    const int sub  = threadIdx.x >> 6;
    const int base = blockIdx.x * 256;
    float* out_idx_f = dout + OUT_IDX;

    float lsum = 0.f;
    #pragma unroll 4
    for (int it = 0; it < 64; ++it) {
        int t   = base + it * 4 + sub;
        int idx = (int)(unsigned)g_key[t];
        float qv = cb[(size_t)idx * DIM + dim];
        float xv = x[(size_t)t * DIM + dim];
        float df = qv - xv;
        dout[OUT_Q + (size_t)t * DIM + dim] = xv + df;
        lsum = fmaf(df, df, lsum);
        if (dim == 0) {
            atomicAdd(&sbins[idx], 1);
            out_idx_f[t] = (float)idx;
        }
    }

    #pragma unroll
    for (int o = 16; o > 0; o >>= 1) lsum += __shfl_down_sync(0xffffffffu, lsum, o);
    if ((threadIdx.x & 31) == 0) swarp[threadIdx.x >> 5] = lsum;
    __syncthreads();
    if (threadIdx.x == 0) {
        float s = 0.f;
        #pragma unroll
        for (int w = 0; w < 8; ++w) s += swarp[w];
        g_block_sse[blockIdx.x] = (double)s;
    }
    for (int i = threadIdx.x; i < KCODES; i += 256) {
        int c = sbins[i];
        if (c) atomicAdd(&g_counts[i], c);
    }
}

// ---------------- kernel 3: finalize loss + perplexity -------------------
__global__ void vq_finalize_kernel(float* __restrict__ dout) {
    __shared__ double sd[256];
    const int tid = threadIdx.x;

    double s = 0.0;
    for (int i = tid; i < QBLOCKS; i += 256) s += g_block_sse[i];
    sd[tid] = s;
    __syncthreads();
    #pragma unroll
    for (int o = 128; o > 0; o >>= 1) {
        if (tid < o) sd[tid] += sd[tid + o];
        __syncthreads();
    }
    double sse = sd[0];
    __syncthreads();

    double h = 0.0;
    for (int i = tid; i < KCODES; i += 256) {
        float p = (float)g_counts[i] * (1.0f / (float)N_TOK);
        h += (double)(p * logf(p + 1e-10f));
    }
    sd[tid] = h;
    __syncthreads();
    #pragma unroll
    for (int o = 128; o > 0; o >>= 1) {
        if (tid < o) sd[tid] += sd[tid + o];
        __syncthreads();
    }

    if (tid == 0) {
        float mse = (float)(sse / ((double)N_TOK * (double)DIM));
        dout[0]        = mse + 0.25f * mse;
        dout[OUT_PERP] = expf((float)(-sd[0]));
    }
}

// ---------------- launch ---------------------------------------------------
extern "C" void kernel_launch(void* const* d_in, const int* in_sizes, int n_in,
                              void* d_out, int out_size) {
    const float* x  = (const float*)d_in[0];
    const float* cb = (const float*)d_in[1];
    if (n_in >= 2 && in_sizes[0] == KCODES * DIM && in_sizes[1] == N_TOK * DIM) {
        const float* t = x; x = cb; cb = t;
    }
    float* out = (float*)d_out;

    cudaFuncSetAttribute(vq_argmin_kernel,
                         cudaFuncAttributeMaxDynamicSharedMemorySize, SMEM_SZ);

    vq_prep_kernel<<<N_TOK / 256, 256>>>(x, cb);
    vq_argmin_kernel<<<(N_TOK / 128) * 2, 128, SMEM_SZ>>>(x, cb);
    vq_quantize_kernel<<<QBLOCKS, 256>>>(x, cb, out);
    vq_finalize_kernel<<<1, 256>>>(out);
}